// round 11
// baseline (speedup 1.0000x reference)
#include <cuda_runtime.h>
#include <cuda_bf16.h>
#include <cstdint>

// Problem: B=4, L=2048, H=8, D=64.
// Reference math collapses: out[b,q,h,d] = (sum_w softmax[.]) * (sum_e V[b,e,h,d])
//                                        = 1 * sum_l V[b,l,h,d]
// Q, K are dead inputs. Column-sum V over L, broadcast over q.
//
// R10: single fused kernel. Evidence from R7/R9: every stage-1 variant
// (LDG scalar/f4, TMA) pins at ~2.5 TB/s => the ~5000-cyc per-launch fixed
// overhead x3 launches + graph gaps dominates, not SM-side memory behavior.
// One launch + software grid barriers (provably co-resident single wave).

#define B_DIM 4
#define L_DIM 2048
#define HD4 128                 // H*D/4 float4 per (b,l) row
#define NBLK 512
#define NTHR 256
#define ROWS 16                 // V rows per block chunk (32 KB)
#define CHUNKS_PER_B 128        // 2048 / 16
#define TILE_BYTES (ROWS * HD4 * 16)   // 32768
#define S2_GROUPS 8             // mids per batch (16 chunks each)

// Scratch (allocation-free __device__ globals)
__device__ float4 g_partial[B_DIM * CHUNKS_PER_B * HD4];  // 1 MB (L2)
__device__ float4 g_mid[B_DIM * S2_GROUPS * HD4];         // 16 KB
__device__ float4 g_vsum[B_DIM * HD4];                    // 8 KB
__device__ unsigned g_count = 0;
__device__ unsigned g_gen = 0;    // monotonic across launches/replays

__device__ __forceinline__ float4 f4add(float4 a, float4 b) {
    a.x += b.x; a.y += b.y; a.z += b.z; a.w += b.w; return a;
}
__device__ __forceinline__ float4 ldcg4(const float4* p) {
    float4 v;
    asm volatile("ld.global.cg.v4.f32 {%0,%1,%2,%3}, [%4];"
                 : "=f"(v.x), "=f"(v.y), "=f"(v.z), "=f"(v.w) : "l"(p));
    return v;
}
__device__ __forceinline__ uint32_t smem_u32(const void* p) {
    return (uint32_t)__cvta_generic_to_shared(p);
}

// Generation-based grid barrier. Safe across graph replays (gen is monotonic,
// count returns to 0 at each release). Requires all NBLK CTAs co-resident:
// 512 CTAs, occ_lim >= 4 (smem ~37KB, 8 warps) -> single wave on 148 SMs.
__device__ __forceinline__ void grid_barrier() {
    __syncthreads();
    if (threadIdx.x == 0) {
        __threadfence();
        unsigned gen = atomicAdd(&g_gen, 0u);
        unsigned arv = atomicAdd(&g_count, 1u);
        if (arv == NBLK - 1u) {
            atomicExch(&g_count, 0u);
            __threadfence();
            atomicAdd(&g_gen, 1u);      // release
        } else {
            while (atomicAdd(&g_gen, 0u) == gen) { }
        }
    }
    __syncthreads();
}

__global__ void __launch_bounds__(NTHR) fused_kernel(const float* __restrict__ V,
                                                     float* __restrict__ out) {
    __shared__ alignas(128) float4 tile[ROWS * HD4];   // 32 KB (reused ph1/ph3)
    __shared__ float4 sdata[NTHR];                     // 4 KB
    __shared__ alignas(8) uint64_t mbar;

    const int blk = blockIdx.x;
    const int t = threadIdx.x;
    const int c = t & 127;          // float4 column
    const int p = t >> 7;           // row-half 0/1

    // ---------------- Phase 1: chunk reduce (all 512 blocks) ----------------
    {
        const int b = blk >> 7;                 // 128 chunks per batch
        const int chunk = blk & 127;
        const uint32_t mb = smem_u32(&mbar);
        if (t == 0) {
            asm volatile("mbarrier.init.shared.b64 [%0], 1;" :: "r"(mb) : "memory");
        }
        __syncthreads();
        if (t == 0) {
            asm volatile("mbarrier.arrive.expect_tx.shared.b64 _, [%0], %1;"
                         :: "r"(mb), "r"((uint32_t)TILE_BYTES) : "memory");
            const float* src = V + ((size_t)(b * L_DIM + chunk * ROWS)) * (HD4 * 4);
            asm volatile(
                "cp.async.bulk.shared::cluster.global.mbarrier::complete_tx::bytes "
                "[%0], [%1], %2, [%3];"
                :: "r"(smem_u32(tile)), "l"(src), "r"((uint32_t)TILE_BYTES), "r"(mb)
                : "memory");
        }
        // wait parity 0 (mbar re-inited each launch)
        uint32_t done = 0;
        do {
            asm volatile(
                "{\n\t.reg .pred p;\n\t"
                "mbarrier.try_wait.parity.shared.b64 p, [%1], 0;\n\t"
                "selp.b32 %0, 1, 0, p;\n\t}"
                : "=r"(done) : "r"(mb) : "memory");
        } while (!done);

        // thread (p,c) sums rows [p*8, p*8+8) of column c; fold halves via smem
        float4 a0 = f4add(tile[(p * 8 + 0) * HD4 + c], tile[(p * 8 + 1) * HD4 + c]);
        float4 a1 = f4add(tile[(p * 8 + 2) * HD4 + c], tile[(p * 8 + 3) * HD4 + c]);
        float4 a2 = f4add(tile[(p * 8 + 4) * HD4 + c], tile[(p * 8 + 5) * HD4 + c]);
        float4 a3 = f4add(tile[(p * 8 + 6) * HD4 + c], tile[(p * 8 + 7) * HD4 + c]);
        sdata[t] = f4add(f4add(a0, a1), f4add(a2, a3));
        __syncthreads();
        if (t < 128)
            g_partial[(b * CHUNKS_PER_B + chunk) * HD4 + t] =
                f4add(sdata[t], sdata[t + 128]);
    }
    grid_barrier();

    // ---------------- Phase 2: mids (32 blocks) ----------------
    if (blk < B_DIM * S2_GROUPS && t < 128) {
        const int b = blk >> 3;
        const int g = blk & 7;
        const float4* src = g_partial + (b * CHUNKS_PER_B + g * 16) * HD4 + t;
        float4 a0 = make_float4(0.f, 0.f, 0.f, 0.f), a1 = a0, a2 = a0, a3 = a0;
#pragma unroll
        for (int k = 0; k < 16; k += 4) {
            a0 = f4add(a0, ldcg4(src + (k + 0) * HD4));
            a1 = f4add(a1, ldcg4(src + (k + 1) * HD4));
            a2 = f4add(a2, ldcg4(src + (k + 2) * HD4));
            a3 = f4add(a3, ldcg4(src + (k + 3) * HD4));
        }
        g_mid[(b * S2_GROUPS + g) * HD4 + t] = f4add(f4add(a0, a1), f4add(a2, a3));
    }
    grid_barrier();

    // ---------------- Phase 2b: vsum (4 blocks) ----------------
    if (blk < B_DIM && t < 128) {
        const float4* m = g_mid + blk * S2_GROUPS * HD4 + t;
        float4 v = f4add(f4add(f4add(ldcg4(m + 0 * HD4), ldcg4(m + 1 * HD4)),
                               f4add(ldcg4(m + 2 * HD4), ldcg4(m + 3 * HD4))),
                         f4add(f4add(ldcg4(m + 4 * HD4), ldcg4(m + 5 * HD4)),
                               f4add(ldcg4(m + 6 * HD4), ldcg4(m + 7 * HD4))));
        g_vsum[blk * HD4 + t] = v;
    }
    grid_barrier();

    // ---------------- Phase 3: broadcast write (all 512 blocks) ----------------
    {
        const int b = blk >> 7;
        const int q0 = (blk & 127) * ROWS;
        const float4 v = ldcg4(&g_vsum[b * HD4 + c]);   // 2 KB L2-hot per block
#pragma unroll
        for (int i = 0; i < 8; ++i)
            tile[(p * 8 + i) * HD4 + c] = v;            // STS.128, conflict-free
        __syncthreads();
        if (t == 0) {
            asm volatile("fence.proxy.async;" ::: "memory");
            float* dst = out + ((size_t)(b * L_DIM + q0)) * (HD4 * 4);
            asm volatile(
                "cp.async.bulk.global.shared::cta.bulk_group [%0], [%1], %2;"
                :: "l"(dst), "r"(smem_u32(tile)), "r"((uint32_t)TILE_BYTES)
                : "memory");
            asm volatile("cp.async.bulk.commit_group;" ::: "memory");
            asm volatile("cp.async.bulk.wait_group 0;" ::: "memory");
        }
    }
}

extern "C" void kernel_launch(void* const* d_in, const int* in_sizes, int n_in,
                              void* d_out, int out_size) {
    // inputs: [0] queries, [1] keys, [2] values (float32). Q, K unused by the math.
    const float* V = (const float*)d_in[2];
    float* out = (float*)d_out;
    fused_kernel<<<NBLK, NTHR>>>(V, out);
}